// round 3
// baseline (speedup 1.0000x reference)
#include <cuda_runtime.h>

#define NE    100
#define D     240
#define D4    60
#define D8    30          // 32-byte chunks per row
#define MROWS 4096
#define HID   256
#define NC    112
#define EDIM  64
#define GRID2 296

// Expanded gates scratch: [NE, D] floats (96 KB).
__device__ float g_gf[NE * D];

// Closed-form GATE_IDX for IRREPS [(64,1),(32,3),(16,5)]
__device__ __forceinline__ int gate_idx(int t) {
    if (t < 64)  return t;
    if (t < 160) return 64 + (t - 64) / 3;
    return 96 + (t - 160) / 5;
}

// ---------------- Kernel 1: tiny MLP, one block per edge, 4-way split-K ----
__global__ void __launch_bounds__(1024) mlp_kernel(
        const float* __restrict__ e_feat,
        const float* __restrict__ W1, const float* __restrict__ b1,
        const float* __restrict__ W2, const float* __restrict__ b2,
        const float* __restrict__ W3, const float* __restrict__ b3) {
    __shared__ float sh_e[EDIM];
    __shared__ float sh_h1[HID];
    __shared__ float sh_h2[HID];
    __shared__ float sh_part[4][HID];
    __shared__ float sh_g[NC];

    const int e   = blockIdx.x;
    const int tid = threadIdx.x;
    const int o   = tid & 255;
    const int s   = tid >> 8;

    if (tid < EDIM) sh_e[tid] = e_feat[e * EDIM + tid];
    __syncthreads();

    {
        float acc = 0.0f;
        const int k0 = s * 16;
        #pragma unroll
        for (int k = 0; k < 16; ++k)
            acc = fmaf(sh_e[k0 + k], W1[(k0 + k) * HID + o], acc);
        sh_part[s][o] = acc;
    }
    __syncthreads();
    if (tid < HID) {
        float v = sh_part[0][tid] + sh_part[1][tid] + sh_part[2][tid] + sh_part[3][tid] + b1[tid];
        sh_h1[tid] = fmaxf(v, 0.0f);
    }
    __syncthreads();

    {
        float acc = 0.0f;
        const int k0 = s * 64;
        #pragma unroll 8
        for (int k = 0; k < 64; ++k)
            acc = fmaf(sh_h1[k0 + k], W2[(k0 + k) * HID + o], acc);
        sh_part[s][o] = acc;
    }
    __syncthreads();
    if (tid < HID) {
        float v = sh_part[0][tid] + sh_part[1][tid] + sh_part[2][tid] + sh_part[3][tid] + b2[tid];
        sh_h2[tid] = fmaxf(v, 0.0f);
    }
    __syncthreads();

    if (o < NC) {
        float acc = 0.0f;
        const int k0 = s * 64;
        #pragma unroll 8
        for (int k = 0; k < 64; ++k)
            acc = fmaf(sh_h2[k0 + k], W3[(k0 + k) * NC + o], acc);
        sh_part[s][o] = acc;
    }
    __syncthreads();
    if (tid < NC) {
        sh_g[tid] = sh_part[0][tid] + sh_part[1][tid] + sh_part[2][tid] + sh_part[3][tid] + b3[tid];
    }
    __syncthreads();

    if (tid < D) g_gf[e * D + tid] = sh_g[gate_idx(tid)];
}

// ---------------- Kernel 2: register-resident broadcast multiply ------------
// out[m, e, d] = x[m, d] * gf[e, d]
// warp = e-group (32 warps), lane = fixed 32B d-chunk (30 of 32 active).
// Gates live in REGISTERS (<=32), inner loop = 8 FMUL + 1 STG.256 per e.
// No shared memory, no per-element LDG.
__global__ void __launch_bounds__(1024, 1) bcast_kernel(const float* __restrict__ x,
                                                        float* __restrict__ out) {
    const int lane = threadIdx.x & 31;   // d8 chunk 0..31 (<30 active)
    const int eg   = threadIdx.x >> 5;   // warp id = e-group 0..31
    if (lane >= D8) return;

    // Preload this thread's gate slices into registers: e = eg + 32k
    const int ne = (eg + 96 < NE) ? 4 : 3;
    float g[4][8];
    #pragma unroll
    for (int k = 0; k < 4; ++k) {
        if (k < ne) {
            const float4* p = reinterpret_cast<const float4*>(&g_gf[(eg + 32 * k) * D + lane * 8]);
            const float4 a = p[0];
            const float4 b = p[1];
            g[k][0] = a.x; g[k][1] = a.y; g[k][2] = a.z; g[k][3] = a.w;
            g[k][4] = b.x; g[k][5] = b.y; g[k][6] = b.z; g[k][7] = b.w;
        }
    }

    const float4* x4 = reinterpret_cast<const float4*>(x);

    for (int m = blockIdx.x; m < MROWS; m += GRID2) {
        const float4 xa = __ldg(&x4[m * D4 + lane * 2]);
        const float4 xb = __ldg(&x4[m * D4 + lane * 2 + 1]);
        const float xv[8] = {xa.x, xa.y, xa.z, xa.w, xb.x, xb.y, xb.z, xb.w};
        float* orow = out + (size_t)m * (NE * D) + lane * 8;
        #pragma unroll
        for (int k = 0; k < 4; ++k) {
            if (k >= ne) break;
            float r[8];
            #pragma unroll
            for (int j = 0; j < 8; ++j) r[j] = g[k][j] * xv[j];
            float* p = orow + (eg + 32 * k) * D;
            asm volatile("st.global.v8.f32 [%0], {%1,%2,%3,%4,%5,%6,%7,%8};"
                         :: "l"(p),
                            "f"(r[0]), "f"(r[1]), "f"(r[2]), "f"(r[3]),
                            "f"(r[4]), "f"(r[5]), "f"(r[6]), "f"(r[7])
                         : "memory");
        }
    }
}

extern "C" void kernel_launch(void* const* d_in, const int* in_sizes, int n_in,
                              void* d_out, int out_size) {
    const float* x      = (const float*)d_in[0];
    const float* e_feat = (const float*)d_in[1];
    const float* W1     = (const float*)d_in[2];
    const float* b1     = (const float*)d_in[3];
    const float* W2     = (const float*)d_in[4];
    const float* b2     = (const float*)d_in[5];
    const float* W3     = (const float*)d_in[6];
    const float* b3     = (const float*)d_in[7];
    float* out = (float*)d_out;

    mlp_kernel<<<NE, 1024>>>(e_feat, W1, b1, W2, b2, W3, b3);
    bcast_kernel<<<GRID2, 1024>>>(x, out);
}